// round 3
// baseline (speedup 1.0000x reference)
#include <cuda_runtime.h>
#include <cstdint>

#define T_TOK 16384
#define E_EXP 8
#define MASK_ELEMS (E_EXP * 2 * T_TOK)   // 262144

// ---------------- device scratch (no allocations allowed) ----------------
__device__ int   g_mdtype;               // 0 = uint8, 1 = int32, 2 = float32
__device__ int   g_counts[E_EXP];
__device__ int   g_idx[E_EXP * T_TOK];
__device__ float g_wts[E_EXP * T_TOK];
__device__ float g_hA[T_TOK * 256];      // stage-1 output accumulator [T, 256]
__device__ float g_hB[T_TOK * 256];      // stage-2 output accumulator [T, 256]

// ---------------- mask dtype detection ----------------
// One-hot mask has exactly T*K = 32768 nonzero entries total.
// If stored as uint8: the first 262144 bytes ARE the whole array -> exactly
// 32768 nonzero bytes. If int32/float32: first 262144 bytes cover only 4 of
// 16 (e,k) planes -> far fewer nonzero bytes. Disambiguate i32/f32 by the
// first nonzero 32-bit word (1 vs 0x3F800000).
__global__ void detect_dtype_kernel(const unsigned char* __restrict__ m) {
    __shared__ int cnt;
    if (threadIdx.x == 0) cnt = 0;
    __syncthreads();
    int local = 0;
    for (int i = threadIdx.x; i < MASK_ELEMS; i += blockDim.x)
        local += (m[i] != 0);
    atomicAdd(&cnt, local);
    __syncthreads();
    if (threadIdx.x == 0) {
        if (cnt == T_TOK * 2) {
            g_mdtype = 0;
        } else {
            const unsigned int* w = reinterpret_cast<const unsigned int*>(m);
            int dt = 1;
            for (int i = 0; i < MASK_ELEMS / 4; i++) {
                if (w[i] != 0u) { dt = (w[i] == 1u) ? 1 : 2; break; }
            }
            g_mdtype = dt;
        }
    }
}

// ---------------- zero kernels ----------------
__global__ void zero_all_kernel(float* __restrict__ out) {
    const float4 z = make_float4(0.f, 0.f, 0.f, 0.f);
    int i0 = blockIdx.x * blockDim.x + threadIdx.x;
    int stride = gridDim.x * blockDim.x;
    float4* a = reinterpret_cast<float4*>(g_hA);
    float4* b = reinterpret_cast<float4*>(g_hB);
    float4* o = reinterpret_cast<float4*>(out);
    const int nab = T_TOK * 256 / 4;
    const int no  = T_TOK * 512 / 4;
    for (int i = i0; i < nab; i += stride) { a[i] = z; b[i] = z; }
    for (int i = i0; i < no;  i += stride) { o[i] = z; }
}

__global__ void zero_counts_kernel() {
    if (threadIdx.x < E_EXP) g_counts[threadIdx.x] = 0;
}

// ---------------- routing: build per-expert token lists ----------------
// logical mask layout [E, K, T], rw layout [T, K]
__device__ __forceinline__ float mask_at(const void* mv, int dt, size_t idx) {
    if (dt == 0) return ((const unsigned char*)mv)[idx] ? 1.f : 0.f;
    if (dt == 1) return ((const int*)mv)[idx] ? 1.f : 0.f;
    return (((const float*)mv)[idx] != 0.f) ? 1.f : 0.f;
}

__global__ void route_kernel(const void* __restrict__ mask,
                             const float* __restrict__ rw) {
    int t = blockIdx.x * blockDim.x + threadIdx.x;
    if (t >= T_TOK) return;
    const int dt = g_mdtype;
    float r0 = rw[2 * t + 0];
    float r1 = rw[2 * t + 1];
#pragma unroll
    for (int e = 0; e < E_EXP; e++) {
        float m0 = mask_at(mask, dt, (size_t)(2 * e + 0) * T_TOK + t);
        float m1 = mask_at(mask, dt, (size_t)(2 * e + 1) * T_TOK + t);
        float c = m0 * r0 + m1 * r1;
        if (c != 0.f || m0 != 0.f || m1 != 0.f) {
            int p = atomicAdd(&g_counts[e], 1);
            g_idx[e * T_TOK + p] = t;
            g_wts[e * T_TOK + p] = c;
        }
    }
}

// ---------------- grouped gathered GEMM + scaled scatter-add epilogue ----
// A:    [T, Kdim] token-major activations (gathered via g_idx)
// W:    [E, Ndim, Kdim]  (out = h @ W_e^T + b_e)
// Out:  [T, Ndim] accumulator (atomicAdd, <=2 contributions per element)
template <bool RELU_FIRST>
__global__ void __launch_bounds__(256)
moe_gemm_kernel(const float* __restrict__ A,
                const float* __restrict__ W,
                const float* __restrict__ bias,
                float* __restrict__ Out,
                int Kdim, int Ndim) {
    const int e   = blockIdx.z;
    const int cnt = g_counts[e];
    const int m0  = blockIdx.y * 64;
    if (m0 >= cnt) return;
    const int n0  = blockIdx.x * 64;

    __shared__ float As[16][68];   // [k][m], pad keeps 16B alignment per row
    __shared__ float Bs[16][68];   // [k][n]
    __shared__ int   toks[64];
    __shared__ float ws[64];

    const int tid = threadIdx.x;
    if (tid < 64) {
        int m = m0 + tid;
        bool live = (m < cnt);
        toks[tid] = live ? g_idx[e * T_TOK + m] : 0;
        ws[tid]   = live ? g_wts[e * T_TOK + m] : 0.f;
    }
    __syncthreads();

    const int lr = tid >> 2;          // 0..63 : tile row (loads)
    const int lc = (tid & 3) << 2;    // 0,4,8,12 : k offset (loads)
    const int tx = tid & 15;          // 0..15 : n micro-tile
    const int ty = tid >> 4;          // 0..15 : m micro-tile

    const float* Arow = A + (size_t)toks[lr] * Kdim + lc;
    const float* Wrow = W + ((size_t)e * Ndim + (n0 + lr)) * (size_t)Kdim + lc;

    float acc[4][4] = {};

    for (int k0 = 0; k0 < Kdim; k0 += 16) {
        float4 av = *reinterpret_cast<const float4*>(Arow + k0);
        float4 bv = *reinterpret_cast<const float4*>(Wrow + k0);
        As[lc + 0][lr] = av.x; As[lc + 1][lr] = av.y;
        As[lc + 2][lr] = av.z; As[lc + 3][lr] = av.w;
        Bs[lc + 0][lr] = bv.x; Bs[lc + 1][lr] = bv.y;
        Bs[lc + 2][lr] = bv.z; Bs[lc + 3][lr] = bv.w;
        __syncthreads();
#pragma unroll
        for (int k = 0; k < 16; k++) {
            float4 a = *reinterpret_cast<const float4*>(&As[k][ty * 4]);
            float4 b = *reinterpret_cast<const float4*>(&Bs[k][tx * 4]);
            acc[0][0] += a.x * b.x; acc[0][1] += a.x * b.y;
            acc[0][2] += a.x * b.z; acc[0][3] += a.x * b.w;
            acc[1][0] += a.y * b.x; acc[1][1] += a.y * b.y;
            acc[1][2] += a.y * b.z; acc[1][3] += a.y * b.w;
            acc[2][0] += a.z * b.x; acc[2][1] += a.z * b.y;
            acc[2][2] += a.z * b.z; acc[2][3] += a.z * b.w;
            acc[3][0] += a.w * b.x; acc[3][1] += a.w * b.y;
            acc[3][2] += a.w * b.z; acc[3][3] += a.w * b.w;
        }
        __syncthreads();
    }

    // epilogue: bias, optional relu (before combine), weight, scatter-add
#pragma unroll
    for (int i = 0; i < 4; i++) {
        int mrow = ty * 4 + i;
        int m = m0 + mrow;
        if (m < cnt) {
            int t   = toks[mrow];
            float w = ws[mrow];
            float* orow = Out + (size_t)t * Ndim + n0 + tx * 4;
            const float* brow = bias + (size_t)e * Ndim + n0 + tx * 4;
#pragma unroll
            for (int j = 0; j < 4; j++) {
                float v = acc[i][j] + brow[j];
                if (RELU_FIRST) v = fmaxf(v, 0.f);
                atomicAdd(&orow[j], w * v);
            }
        }
    }
}

// ---------------- final relu ----------------
__global__ void relu_inplace_kernel(float* __restrict__ out, int n4) {
    int i0 = blockIdx.x * blockDim.x + threadIdx.x;
    int stride = gridDim.x * blockDim.x;
    float4* p = reinterpret_cast<float4*>(out);
    for (int i = i0; i < n4; i += stride) {
        float4 v = p[i];
        v.x = fmaxf(v.x, 0.f); v.y = fmaxf(v.y, 0.f);
        v.z = fmaxf(v.z, 0.f); v.w = fmaxf(v.w, 0.f);
        p[i] = v;
    }
}

// ---------------- launch ----------------
extern "C" void kernel_launch(void* const* d_in, const int* in_sizes, int n_in,
                              void* d_out, int out_size) {
    const float* x   = (const float*)d_in[0];
    const void*  m1  = d_in[1];
    const void*  m2  = d_in[2];
    const void*  m3  = d_in[3];
    const float* rw1 = (const float*)d_in[4];
    const float* rw2 = (const float*)d_in[5];
    const float* rw3 = (const float*)d_in[6];
    const float* W1  = (const float*)d_in[7];
    const float* b1  = (const float*)d_in[8];
    const float* W2  = (const float*)d_in[9];
    const float* b2  = (const float*)d_in[10];
    const float* W3  = (const float*)d_in[11];
    const float* b3  = (const float*)d_in[12];
    float* out = (float*)d_out;

    // device-scratch addresses (no allocation; symbols live in the module)
    void *hA_p = nullptr, *hB_p = nullptr;
    cudaGetSymbolAddress(&hA_p, g_hA);
    cudaGetSymbolAddress(&hB_p, g_hB);
    float* hA = (float*)hA_p;
    float* hB = (float*)hB_p;

    detect_dtype_kernel<<<1, 256>>>((const unsigned char*)m1);
    zero_all_kernel<<<512, 256>>>(out);

    // ---- stage 1: x[.,512] -> hA[.,256], no activation ----
    zero_counts_kernel<<<1, 32>>>();
    route_kernel<<<T_TOK / 256, 256>>>(m1, rw1);
    {
        dim3 grid(256 / 64, T_TOK / 64, E_EXP);
        moe_gemm_kernel<false><<<grid, 256>>>(x, W1, b1, hA, 512, 256);
    }

    // ---- stage 2: hA[.,256] -> hB[.,256], no activation ----
    zero_counts_kernel<<<1, 32>>>();
    route_kernel<<<T_TOK / 256, 256>>>(m2, rw2);
    {
        dim3 grid(256 / 64, T_TOK / 64, E_EXP);
        moe_gemm_kernel<false><<<grid, 256>>>(hA, W2, b2, hB, 256, 256);
    }

    // ---- stage 3: hB[.,256] -> out[.,512], relu on expert output ----
    zero_counts_kernel<<<1, 32>>>();
    route_kernel<<<T_TOK / 256, 256>>>(m3, rw3);
    {
        dim3 grid(512 / 64, T_TOK / 64, E_EXP);
        moe_gemm_kernel<true><<<grid, 256>>>(hB, W3, b3, out, 256, 512);
    }

    // ---- final relu on combined output ----
    relu_inplace_kernel<<<512, 256>>>(out, T_TOK * 512 / 4);
}

// round 13
// speedup vs baseline: 1.7835x; 1.7835x over previous
#include <cuda_runtime.h>
#include <cuda_bf16.h>
#include <cstdint>

#define T_TOK 16384
#define E_EXP 8
#define MASK_ELEMS (E_EXP * 2 * T_TOK)   // 262144

// ===================== portable PTX helpers (sm_80+ features only) ==========
__device__ __forceinline__ uint32_t smem_to_u32(const void* smem_ptr) {
    uint32_t addr;
    asm("{ .reg .u64 tmp; cvta.to.shared.u64 tmp, %1; cvt.u32.u64 %0, tmp; }"
        : "=r"(addr) : "l"(smem_ptr));
    return addr;
}

#define CP_ASYNC16(dst_u32, src_ptr) \
    asm volatile("cp.async.cg.shared.global [%0], [%1], 16;" \
        :: "r"(dst_u32), "l"(src_ptr))
#define CP_COMMIT() asm volatile("cp.async.commit_group;" ::: "memory")
#define CP_WAIT(n)  asm volatile("cp.async.wait_group %0;" :: "n"(n) : "memory")

__device__ __forceinline__ void ldsm4(uint32_t& r0, uint32_t& r1,
                                      uint32_t& r2, uint32_t& r3, uint32_t addr) {
    asm volatile("ldmatrix.sync.aligned.m8n8.x4.shared.b16 {%0,%1,%2,%3}, [%4];"
        : "=r"(r0), "=r"(r1), "=r"(r2), "=r"(r3) : "r"(addr));
}

__device__ __forceinline__ void mma16816(float* c, const uint32_t* a,
                                         uint32_t b0, uint32_t b1) {
    asm volatile(
        "mma.sync.aligned.m16n8k16.row.col.f32.bf16.bf16.f32 "
        "{%0,%1,%2,%3}, {%4,%5,%6,%7}, {%8,%9}, {%0,%1,%2,%3};"
        : "+f"(c[0]), "+f"(c[1]), "+f"(c[2]), "+f"(c[3])
        : "r"(a[0]), "r"(a[1]), "r"(a[2]), "r"(a[3]), "r"(b0), "r"(b1));
}

// ===================== device scratch =====================
__device__ int   g_mdtype;
__device__ int   g_cnt[3][E_EXP];
__device__ int   g_idxs[3][E_EXP * T_TOK];
__device__ int2   g_ent[3][T_TOK];
__device__ float2 g_wtk[3][T_TOK];

__device__ __nv_bfloat16 g_xh[T_TOK * 512],  g_xl[T_TOK * 512];
__device__ __nv_bfloat16 g_h1h[T_TOK * 256], g_h1l[T_TOK * 256];
__device__ __nv_bfloat16 g_h2h[T_TOK * 256], g_h2l[T_TOK * 256];
__device__ __nv_bfloat16 g_w1h[E_EXP * 256 * 512], g_w1l[E_EXP * 256 * 512];
__device__ __nv_bfloat16 g_w2h[E_EXP * 256 * 256], g_w2l[E_EXP * 256 * 256];
__device__ __nv_bfloat16 g_w3h[E_EXP * 512 * 256], g_w3l[E_EXP * 512 * 256];
__device__ float g_Y[(size_t)E_EXP * T_TOK * 512];   // per-entry expert outputs

// ===================== mask dtype detection =====================
__global__ void detect_dtype_kernel(const unsigned char* __restrict__ m) {
    __shared__ int cnt;
    if (threadIdx.x == 0) cnt = 0;
    __syncthreads();
    int local = 0;
    for (int i = threadIdx.x; i < MASK_ELEMS; i += blockDim.x)
        local += (m[i] != 0);
    atomicAdd(&cnt, local);
    __syncthreads();
    if (threadIdx.x == 0) {
        if (cnt == T_TOK * 2) {
            g_mdtype = 0;
        } else {
            const unsigned int* w = reinterpret_cast<const unsigned int*>(m);
            int dt = 1;
            for (int i = 0; i < MASK_ELEMS / 4; i++) {
                if (w[i] != 0u) { dt = (w[i] == 1u) ? 1 : 2; break; }
            }
            g_mdtype = dt;
        }
    }
}

__global__ void zero_cnt_kernel() {
    if (threadIdx.x < 24) ((int*)g_cnt)[threadIdx.x] = 0;
}

// ===================== routing (warp-aggregated), all 3 stages ==============
__device__ __forceinline__ float mask_at(const void* mv, int dt, size_t idx) {
    if (dt == 0) return ((const unsigned char*)mv)[idx] ? 1.f : 0.f;
    if (dt == 1) return ((const int*)mv)[idx] ? 1.f : 0.f;
    return (((const float*)mv)[idx] != 0.f) ? 1.f : 0.f;
}

__global__ void route3_kernel(const void* __restrict__ m1, const void* __restrict__ m2,
                              const void* __restrict__ m3,
                              const float* __restrict__ rw1, const float* __restrict__ rw2,
                              const float* __restrict__ rw3) {
    int t = blockIdx.x * blockDim.x + threadIdx.x;
    int lane = threadIdx.x & 31;
    const int dt = g_mdtype;
    const void*  masks[3] = {m1, m2, m3};
    const float* rws[3]   = {rw1, rw2, rw3};
#pragma unroll
    for (int s = 0; s < 3; s++) {
        float r0 = rws[s][2 * t + 0];
        float r1 = rws[s][2 * t + 1];
        int slot = 0, e0i = 0, e1i = -1;
        float w0 = 0.f, w1 = 0.f;
#pragma unroll
        for (int e = 0; e < E_EXP; e++) {
            float mm0 = mask_at(masks[s], dt, (size_t)(2 * e + 0) * T_TOK + t);
            float mm1 = mask_at(masks[s], dt, (size_t)(2 * e + 1) * T_TOK + t);
            bool rt = (mm0 != 0.f) || (mm1 != 0.f);
            unsigned bal = __ballot_sync(0xffffffffu, rt);
            if (bal) {
                int leader = __ffs(bal) - 1;
                int base = 0;
                if (lane == leader) base = atomicAdd(&g_cnt[s][e], __popc(bal));
                base = __shfl_sync(0xffffffffu, base, leader);
                if (rt) {
                    int p = base + __popc(bal & ((1u << lane) - 1u));
                    g_idxs[s][e * T_TOK + p] = t;
                    float c = mm0 * r0 + mm1 * r1;
                    if (slot == 0) { e0i = e * T_TOK + p; w0 = c; }
                    else           { e1i = e * T_TOK + p; w1 = c; }
                    slot++;
                }
            }
        }
        g_ent[s][t] = make_int2(e0i, e1i);
        g_wtk[s][t] = make_float2(w0, w1);
    }
}

// ===================== fp32 -> bf16 hi/lo split =====================
__device__ __forceinline__ void split2(float a, float b, __nv_bfloat162& h, __nv_bfloat162& l) {
    __nv_bfloat16 ha = __float2bfloat16(a), hb = __float2bfloat16(b);
    __nv_bfloat16 la = __float2bfloat16(a - __bfloat162float(ha));
    __nv_bfloat16 lb = __float2bfloat16(b - __bfloat162float(hb));
    h = __nv_bfloat162(ha, hb);
    l = __nv_bfloat162(la, lb);
}

__global__ void cvt_pair_kernel(const float* __restrict__ in,
                                __nv_bfloat16* __restrict__ oh,
                                __nv_bfloat16* __restrict__ ol, int n4) {
    int i = blockIdx.x * blockDim.x + threadIdx.x;
    if (i >= n4) return;
    float4 v = reinterpret_cast<const float4*>(in)[i];
    __nv_bfloat162 h0, l0, h1, l1;
    split2(v.x, v.y, h0, l0);
    split2(v.z, v.w, h1, l1);
    reinterpret_cast<__nv_bfloat162*>(oh)[2 * i + 0] = h0;
    reinterpret_cast<__nv_bfloat162*>(oh)[2 * i + 1] = h1;
    reinterpret_cast<__nv_bfloat162*>(ol)[2 * i + 0] = l0;
    reinterpret_cast<__nv_bfloat162*>(ol)[2 * i + 1] = l1;
}

// ===================== HMMA grouped gathered GEMM ===========================
// Y[(e*T + p), n] = sum_k A[tok(p), k] * W[e, n, k]   bf16 hi/lo 3-pass, fp32 acc
// CTA tile 128x128, BK=32, 8 warps (2m x 4n), warp tile 64x32.
// smem: double buffer x 4 tiles (Ah, Al, Wh, Wl), each 128 rows x 40 halves.
#define TILE_B  10240          // 128*40*2 bytes
#define BUF_B   40960          // 4 tiles
#define GEMM_DSMEM (2 * BUF_B) // 81920

template <int KD>
__global__ void __launch_bounds__(256, 1)
moe_gemm_mma(const __nv_bfloat16* __restrict__ Ah, const __nv_bfloat16* __restrict__ Al,
             const __nv_bfloat16* __restrict__ Wh, const __nv_bfloat16* __restrict__ Wl,
             float* __restrict__ Y, const int* __restrict__ cnts,
             const int* __restrict__ gidx, int Ndim) {
    const int e   = blockIdx.z;
    const int cnt = __ldg(&cnts[e]);
    const int m0  = blockIdx.y * 128;
    if (m0 >= cnt) return;
    const int n0  = blockIdx.x * 128;

    extern __shared__ char dsm_raw[];
    const uint32_t dsm = smem_to_u32(dsm_raw);

    __shared__ int toks[128];

    const int tid  = threadIdx.x;
    const int lane = tid & 31;
    const int wid  = tid >> 5;
    const int wm   = wid >> 2;   // 0..1  -> m offset wm*64
    const int wn   = wid & 3;    // 0..3  -> n offset wn*32

    if (tid < 128) {
        int m = m0 + tid;
        toks[tid] = gidx[e * T_TOK + (m < cnt ? m : cnt - 1)];
    }
    __syncthreads();

    const int lr = tid >> 2;     // 0..63 (row base for loads)
    const int lc = tid & 3;      // 0..3  (16B column chunk)

    auto prefetch = [&](int c) {
        const int k0 = c * 32;
        const uint32_t sb = dsm + (uint32_t)(c & 1) * BUF_B;
#pragma unroll
        for (int rep = 0; rep < 2; rep++) {
            int r = lr + rep * 64;
            size_t aoff = (size_t)toks[r] * KD + k0 + lc * 8;
            size_t woff = ((size_t)e * Ndim + n0 + r) * (size_t)KD + k0 + lc * 8;
            uint32_t so = (uint32_t)(r * 40 + lc * 8) * 2;
            CP_ASYNC16(sb + 0 * TILE_B + so, Ah + aoff);
            CP_ASYNC16(sb + 1 * TILE_B + so, Al + aoff);
            CP_ASYNC16(sb + 2 * TILE_B + so, Wh + woff);
            CP_ASYNC16(sb + 3 * TILE_B + so, Wl + woff);
        }
        CP_COMMIT();
    };

    float acc[4][4][4] = {};

    const int NCH = KD / 32;
    prefetch(0);

    for (int c = 0; c < NCH; ++c) {
        if (c + 1 < NCH) { prefetch(c + 1); CP_WAIT(1); }
        else             { CP_WAIT(0); }
        __syncthreads();

        const uint32_t sb = dsm + (uint32_t)(c & 1) * BUF_B;
#pragma unroll
        for (int ks = 0; ks < 32; ks += 16) {
            uint32_t ah[4][4], al[4][4];
#pragma unroll
            for (int mf = 0; mf < 4; mf++) {
                uint32_t row = (uint32_t)(wm * 64 + mf * 16 + (lane & 15));
                uint32_t col = (uint32_t)(ks + ((lane >> 4) << 3));
                uint32_t ad  = sb + (row * 40 + col) * 2;
                ldsm4(ah[mf][0], ah[mf][1], ah[mf][2], ah[mf][3], ad);
                ldsm4(al[mf][0], al[mf][1], al[mf][2], al[mf][3], ad + TILE_B);
            }
            uint32_t bh[2][4], bl[2][4];
#pragma unroll
            for (int np = 0; np < 2; np++) {
                uint32_t nrow = (uint32_t)(wn * 32 + np * 16 + ((lane >> 4) << 3) + (lane & 7));
                uint32_t kcol = (uint32_t)(ks + ((lane >> 3) & 1) * 8);
                uint32_t bd   = sb + 2 * TILE_B + (nrow * 40 + kcol) * 2;
                ldsm4(bh[np][0], bh[np][1], bh[np][2], bh[np][3], bd);
                ldsm4(bl[np][0], bl[np][1], bl[np][2], bl[np][3], bd + TILE_B);
            }
#pragma unroll
            for (int mf = 0; mf < 4; mf++) {
#pragma unroll
                for (int nf = 0; nf < 4; nf++) {
                    uint32_t b0h = bh[nf >> 1][(nf & 1) * 2];
                    uint32_t b1h = bh[nf >> 1][(nf & 1) * 2 + 1];
                    uint32_t b0l = bl[nf >> 1][(nf & 1) * 2];
                    uint32_t b1l = bl[nf >> 1][(nf & 1) * 2 + 1];
                    mma16816(acc[mf][nf], ah[mf], b0h, b1h);
                    mma16816(acc[mf][nf], ah[mf], b0l, b1l);
                    mma16816(acc[mf][nf], al[mf], b0h, b1h);
                }
            }
        }
        __syncthreads();
    }

    // epilogue: write per-entry outputs (no atomics)
#pragma unroll
    for (int mf = 0; mf < 4; mf++) {
        int mrow = wm * 64 + mf * 16 + (lane >> 2);
        bool live0 = (m0 + mrow) < cnt;
        bool live1 = (m0 + mrow + 8) < cnt;
        float* y0 = Y + ((size_t)e * T_TOK + m0 + mrow) * Ndim + n0 + wn * 32 + (lane & 3) * 2;
#pragma unroll
        for (int nf = 0; nf < 4; nf++) {
            if (live0) {
                float2 v = make_float2(acc[mf][nf][0], acc[mf][nf][1]);
                *reinterpret_cast<float2*>(y0 + nf * 8) = v;
            }
            if (live1) {
                float2 v = make_float2(acc[mf][nf][2], acc[mf][nf][3]);
                *reinterpret_cast<float2*>(y0 + (size_t)8 * Ndim + nf * 8) = v;
            }
        }
    }
}

// ===================== combine kernels =====================
__global__ void combine_bf16_kernel(const float* __restrict__ Y, int s,
                                    const float* __restrict__ bias, int Ndim,
                                    __nv_bfloat16* __restrict__ oh,
                                    __nv_bfloat16* __restrict__ ol) {
    int gid = blockIdx.x * blockDim.x + threadIdx.x;
    int per = Ndim >> 2;
    int t = gid / per;
    if (t >= T_TOK) return;
    int c = (gid - t * per) << 2;
    int2 en = g_ent[s][t];
    float2 w = g_wtk[s][t];
    int e0 = en.x >> 14;
    float4 y0 = *(const float4*)(Y + (size_t)en.x * Ndim + c);
    float4 b0 = *(const float4*)(bias + (size_t)e0 * Ndim + c);
    float4 v;
    v.x = w.x * (y0.x + b0.x); v.y = w.x * (y0.y + b0.y);
    v.z = w.x * (y0.z + b0.z); v.w = w.x * (y0.w + b0.w);
    if (en.y >= 0) {
        int e1 = en.y >> 14;
        float4 y1 = *(const float4*)(Y + (size_t)en.y * Ndim + c);
        float4 b1 = *(const float4*)(bias + (size_t)e1 * Ndim + c);
        v.x += w.y * (y1.x + b1.x); v.y += w.y * (y1.y + b1.y);
        v.z += w.y * (y1.z + b1.z); v.w += w.y * (y1.w + b1.w);
    }
    __nv_bfloat162 h0, l0, h1, l1;
    split2(v.x, v.y, h0, l0);
    split2(v.z, v.w, h1, l1);
    size_t o = (size_t)t * Ndim + c;
    *(__nv_bfloat162*)(oh + o)     = h0;
    *(__nv_bfloat162*)(oh + o + 2) = h1;
    *(__nv_bfloat162*)(ol + o)     = l0;
    *(__nv_bfloat162*)(ol + o + 2) = l1;
}

__global__ void combine_final_kernel(const float* __restrict__ Y, int s,
                                     const float* __restrict__ bias, int Ndim,
                                     float* __restrict__ out) {
    int gid = blockIdx.x * blockDim.x + threadIdx.x;
    int per = Ndim >> 2;
    int t = gid / per;
    if (t >= T_TOK) return;
    int c = (gid - t * per) << 2;
    int2 en = g_ent[s][t];
    float2 w = g_wtk[s][t];
    int e0 = en.x >> 14;
    float4 y0 = *(const float4*)(Y + (size_t)en.x * Ndim + c);
    float4 b0 = *(const float4*)(bias + (size_t)e0 * Ndim + c);
    float4 v;
    v.x = w.x * fmaxf(y0.x + b0.x, 0.f); v.y = w.x * fmaxf(y0.y + b0.y, 0.f);
    v.z = w.x * fmaxf(y0.z + b0.z, 0.f); v.w = w.x * fmaxf(y0.w + b0.w, 0.f);
    if (en.y >= 0) {
        int e1 = en.y >> 14;
        float4 y1 = *(const float4*)(Y + (size_t)en.y * Ndim + c);
        float4 b1 = *(const float4*)(bias + (size_t)e1 * Ndim + c);
        v.x += w.y * fmaxf(y1.x + b1.x, 0.f); v.y += w.y * fmaxf(y1.y + b1.y, 0.f);
        v.z += w.y * fmaxf(y1.z + b1.z, 0.f); v.w += w.y * fmaxf(y1.w + b1.w, 0.f);
    }
    v.x = fmaxf(v.x, 0.f); v.y = fmaxf(v.y, 0.f);
    v.z = fmaxf(v.z, 0.f); v.w = fmaxf(v.w, 0.f);
    *(float4*)(out + (size_t)t * Ndim + c) = v;
}

// ===================== launch =====================
extern "C" void kernel_launch(void* const* d_in, const int* in_sizes, int n_in,
                              void* d_out, int out_size) {
    const float* x   = (const float*)d_in[0];
    const void*  m1  = d_in[1];
    const void*  m2  = d_in[2];
    const void*  m3  = d_in[3];
    const float* rw1 = (const float*)d_in[4];
    const float* rw2 = (const float*)d_in[5];
    const float* rw3 = (const float*)d_in[6];
    const float* W1  = (const float*)d_in[7];
    const float* b1  = (const float*)d_in[8];
    const float* W2  = (const float*)d_in[9];
    const float* b2  = (const float*)d_in[10];
    const float* W3  = (const float*)d_in[11];
    const float* b3  = (const float*)d_in[12];
    float* out = (float*)d_out;

    void* p;
    cudaGetSymbolAddress(&p, g_xh);  __nv_bfloat16* xh  = (__nv_bfloat16*)p;
    cudaGetSymbolAddress(&p, g_xl);  __nv_bfloat16* xl  = (__nv_bfloat16*)p;
    cudaGetSymbolAddress(&p, g_h1h); __nv_bfloat16* h1h = (__nv_bfloat16*)p;
    cudaGetSymbolAddress(&p, g_h1l); __nv_bfloat16* h1l = (__nv_bfloat16*)p;
    cudaGetSymbolAddress(&p, g_h2h); __nv_bfloat16* h2h = (__nv_bfloat16*)p;
    cudaGetSymbolAddress(&p, g_h2l); __nv_bfloat16* h2l = (__nv_bfloat16*)p;
    cudaGetSymbolAddress(&p, g_w1h); __nv_bfloat16* w1h = (__nv_bfloat16*)p;
    cudaGetSymbolAddress(&p, g_w1l); __nv_bfloat16* w1l = (__nv_bfloat16*)p;
    cudaGetSymbolAddress(&p, g_w2h); __nv_bfloat16* w2h = (__nv_bfloat16*)p;
    cudaGetSymbolAddress(&p, g_w2l); __nv_bfloat16* w2l = (__nv_bfloat16*)p;
    cudaGetSymbolAddress(&p, g_w3h); __nv_bfloat16* w3h = (__nv_bfloat16*)p;
    cudaGetSymbolAddress(&p, g_w3l); __nv_bfloat16* w3l = (__nv_bfloat16*)p;
    cudaGetSymbolAddress(&p, g_Y);   float* Y = (float*)p;
    cudaGetSymbolAddress(&p, g_cnt);  int* cnt  = (int*)p;
    cudaGetSymbolAddress(&p, g_idxs); int* idxs = (int*)p;

    cudaFuncSetAttribute(moe_gemm_mma<512>, cudaFuncAttributeMaxDynamicSharedMemorySize, GEMM_DSMEM);
    cudaFuncSetAttribute(moe_gemm_mma<256>, cudaFuncAttributeMaxDynamicSharedMemorySize, GEMM_DSMEM);

    detect_dtype_kernel<<<1, 256>>>((const unsigned char*)m1);
    zero_cnt_kernel<<<1, 32>>>();
    route3_kernel<<<T_TOK / 256, 256>>>(m1, m2, m3, rw1, rw2, rw3);

    cvt_pair_kernel<<<(T_TOK * 512 / 4) / 256, 256>>>(x, xh, xl, T_TOK * 512 / 4);
    cvt_pair_kernel<<<(E_EXP * 256 * 512 / 4) / 256, 256>>>(W1, w1h, w1l, E_EXP * 256 * 512 / 4);
    cvt_pair_kernel<<<(E_EXP * 256 * 256 / 4) / 256, 256>>>(W2, w2h, w2l, E_EXP * 256 * 256 / 4);
    cvt_pair_kernel<<<(E_EXP * 512 * 256 / 4) / 256, 256>>>(W3, w3h, w3l, E_EXP * 512 * 256 / 4);

    // stage 1: x[.,512] -> Y -> h1 (bf16 pair)
    {
        dim3 grid(256 / 128, T_TOK / 128, E_EXP);
        moe_gemm_mma<512><<<grid, 256, GEMM_DSMEM>>>(xh, xl, w1h, w1l, Y,
                                                     cnt + 0 * E_EXP, idxs + 0 * E_EXP * T_TOK, 256);
        combine_bf16_kernel<<<(T_TOK * 256 / 4) / 256, 256>>>(Y, 0, b1, 256, h1h, h1l);
    }
    // stage 2: h1[.,256] -> Y -> h2 (bf16 pair)
    {
        dim3 grid(256 / 128, T_TOK / 128, E_EXP);
        moe_gemm_mma<256><<<grid, 256, GEMM_DSMEM>>>(h1h, h1l, w2h, w2l, Y,
                                                     cnt + 1 * E_EXP, idxs + 1 * E_EXP * T_TOK, 256);
        combine_bf16_kernel<<<(T_TOK * 256 / 4) / 256, 256>>>(Y, 1, b2, 256, h2h, h2l);
    }
    // stage 3: h2[.,256] -> Y -> out (relu(expert), combine, relu)
    {
        dim3 grid(512 / 128, T_TOK / 128, E_EXP);
        moe_gemm_mma<256><<<grid, 256, GEMM_DSMEM>>>(h2h, h2l, w3h, w3l, Y,
                                                     cnt + 2 * E_EXP, idxs + 2 * E_EXP * T_TOK, 512);
        combine_final_kernel<<<(T_TOK * 512 / 4) / 256, 256>>>(Y, 2, b3, 512, out);
    }
}

// round 14
// speedup vs baseline: 2.0619x; 1.1561x over previous
#include <cuda_runtime.h>
#include <cuda_bf16.h>
#include <cstdint>

#define T_TOK 16384
#define E_EXP 8
#define MASK_ELEMS (E_EXP * 2 * T_TOK)   // 262144

// ===================== portable PTX helpers (sm_80+ features only) ==========
__device__ __forceinline__ uint32_t smem_to_u32(const void* smem_ptr) {
    uint32_t addr;
    asm("{ .reg .u64 tmp; cvta.to.shared.u64 tmp, %1; cvt.u32.u64 %0, tmp; }"
        : "=r"(addr) : "l"(smem_ptr));
    return addr;
}

#define CP_ASYNC16(dst_u32, src_ptr) \
    asm volatile("cp.async.cg.shared.global [%0], [%1], 16;" \
        :: "r"(dst_u32), "l"(src_ptr))
#define CP_COMMIT() asm volatile("cp.async.commit_group;" ::: "memory")
#define CP_WAIT(n)  asm volatile("cp.async.wait_group %0;" :: "n"(n) : "memory")

__device__ __forceinline__ void ldsm4(uint32_t& r0, uint32_t& r1,
                                      uint32_t& r2, uint32_t& r3, uint32_t addr) {
    asm volatile("ldmatrix.sync.aligned.m8n8.x4.shared.b16 {%0,%1,%2,%3}, [%4];"
        : "=r"(r0), "=r"(r1), "=r"(r2), "=r"(r3) : "r"(addr));
}

__device__ __forceinline__ void mma16816(float* c, const uint32_t* a,
                                         uint32_t b0, uint32_t b1) {
    asm volatile(
        "mma.sync.aligned.m16n8k16.row.col.f32.bf16.bf16.f32 "
        "{%0,%1,%2,%3}, {%4,%5,%6,%7}, {%8,%9}, {%0,%1,%2,%3};"
        : "+f"(c[0]), "+f"(c[1]), "+f"(c[2]), "+f"(c[3])
        : "r"(a[0]), "r"(a[1]), "r"(a[2]), "r"(a[3]), "r"(b0), "r"(b1));
}

// ===================== device scratch =====================
__device__ int   g_mdtype;
__device__ int   g_dtcnt;
__device__ int   g_cnt[3][E_EXP];
__device__ int   g_idxs[3][E_EXP * T_TOK];
__device__ int2   g_ent[3][T_TOK];
__device__ float2 g_wtk[3][T_TOK];

__device__ __nv_bfloat16 g_xh[T_TOK * 512],  g_xl[T_TOK * 512];
__device__ __nv_bfloat16 g_h1h[T_TOK * 256], g_h1l[T_TOK * 256];
__device__ __nv_bfloat16 g_h2h[T_TOK * 256], g_h2l[T_TOK * 256];
__device__ __nv_bfloat16 g_w1h[E_EXP * 256 * 512], g_w1l[E_EXP * 256 * 512];
__device__ __nv_bfloat16 g_w2h[E_EXP * 256 * 256], g_w2l[E_EXP * 256 * 256];
__device__ __nv_bfloat16 g_w3h[E_EXP * 512 * 256], g_w3l[E_EXP * 512 * 256];
__device__ float g_Y[(size_t)E_EXP * T_TOK * 512];   // per-entry expert outputs

// ===================== mask dtype detection (parallel) =====================
__global__ void detect_count_kernel(const unsigned char* __restrict__ m) {
    __shared__ int cnt;
    if (threadIdx.x == 0) cnt = 0;
    __syncthreads();
    int local = 0;
    for (int i = blockIdx.x * blockDim.x + threadIdx.x; i < MASK_ELEMS;
         i += gridDim.x * blockDim.x)
        local += (m[i] != 0);
    atomicAdd(&cnt, local);
    __syncthreads();
    if (threadIdx.x == 0 && cnt) atomicAdd(&g_dtcnt, cnt);
}

__global__ void detect_decide_kernel(const unsigned char* __restrict__ m) {
    if (g_dtcnt == T_TOK * 2) {
        g_mdtype = 0;
    } else {
        const unsigned int* w = reinterpret_cast<const unsigned int*>(m);
        int dt = 1;
        for (int i = 0; i < MASK_ELEMS / 4; i++) {
            if (w[i] != 0u) { dt = (w[i] == 1u) ? 1 : 2; break; }
        }
        g_mdtype = dt;
    }
}

__global__ void zero_cnt_kernel() {
    if (threadIdx.x < 24) ((int*)g_cnt)[threadIdx.x] = 0;
    if (threadIdx.x == 24) g_dtcnt = 0;
}

// ===================== routing (warp-aggregated), all 3 stages ==============
__device__ __forceinline__ float mask_at(const void* mv, int dt, size_t idx) {
    if (dt == 0) return ((const unsigned char*)mv)[idx] ? 1.f : 0.f;
    if (dt == 1) return ((const int*)mv)[idx] ? 1.f : 0.f;
    return (((const float*)mv)[idx] != 0.f) ? 1.f : 0.f;
}

__global__ void route3_kernel(const void* __restrict__ m1, const void* __restrict__ m2,
                              const void* __restrict__ m3,
                              const float* __restrict__ rw1, const float* __restrict__ rw2,
                              const float* __restrict__ rw3) {
    int t = blockIdx.x * blockDim.x + threadIdx.x;
    int lane = threadIdx.x & 31;
    const int dt = g_mdtype;
    const void*  masks[3] = {m1, m2, m3};
    const float* rws[3]   = {rw1, rw2, rw3};
#pragma unroll
    for (int s = 0; s < 3; s++) {
        float r0 = rws[s][2 * t + 0];
        float r1 = rws[s][2 * t + 1];
        int slot = 0, e0i = 0, e1i = -1;
        float w0 = 0.f, w1 = 0.f;
#pragma unroll
        for (int e = 0; e < E_EXP; e++) {
            float mm0 = mask_at(masks[s], dt, (size_t)(2 * e + 0) * T_TOK + t);
            float mm1 = mask_at(masks[s], dt, (size_t)(2 * e + 1) * T_TOK + t);
            bool rt = (mm0 != 0.f) || (mm1 != 0.f);
            unsigned bal = __ballot_sync(0xffffffffu, rt);
            if (bal) {
                int leader = __ffs(bal) - 1;
                int base = 0;
                if (lane == leader) base = atomicAdd(&g_cnt[s][e], __popc(bal));
                base = __shfl_sync(0xffffffffu, base, leader);
                if (rt) {
                    int p = base + __popc(bal & ((1u << lane) - 1u));
                    g_idxs[s][e * T_TOK + p] = t;
                    float c = mm0 * r0 + mm1 * r1;
                    if (slot == 0) { e0i = e * T_TOK + p; w0 = c; }
                    else           { e1i = e * T_TOK + p; w1 = c; }
                    slot++;
                }
            }
        }
        g_ent[s][t] = make_int2(e0i, e1i);
        g_wtk[s][t] = make_float2(w0, w1);
    }
}

// ===================== fp32 -> bf16 hi/lo split =====================
__device__ __forceinline__ void split2(float a, float b, __nv_bfloat162& h, __nv_bfloat162& l) {
    __nv_bfloat16 ha = __float2bfloat16(a), hb = __float2bfloat16(b);
    __nv_bfloat16 la = __float2bfloat16(a - __bfloat162float(ha));
    __nv_bfloat16 lb = __float2bfloat16(b - __bfloat162float(hb));
    h = __nv_bfloat162(ha, hb);
    l = __nv_bfloat162(la, lb);
}

__global__ void cvt_pair_kernel(const float* __restrict__ in,
                                __nv_bfloat16* __restrict__ oh,
                                __nv_bfloat16* __restrict__ ol, int n4) {
    int i = blockIdx.x * blockDim.x + threadIdx.x;
    if (i >= n4) return;
    float4 v = reinterpret_cast<const float4*>(in)[i];
    __nv_bfloat162 h0, l0, h1, l1;
    split2(v.x, v.y, h0, l0);
    split2(v.z, v.w, h1, l1);
    reinterpret_cast<__nv_bfloat162*>(oh)[2 * i + 0] = h0;
    reinterpret_cast<__nv_bfloat162*>(oh)[2 * i + 1] = h1;
    reinterpret_cast<__nv_bfloat162*>(ol)[2 * i + 0] = l0;
    reinterpret_cast<__nv_bfloat162*>(ol)[2 * i + 1] = l1;
}

// ===================== HMMA grouped gathered GEMM ===========================
// Y[(e*T + p), n] = sum_k A[tok(p), k] * W[e, n, k]   bf16 hi/lo 3-pass, fp32 acc
// CTA tile 128x128, BK=32, 8 warps (2m x 4n), warp tile 64x32.
// Pass-outer MMA ordering: 16 independent accumulators between reuses.
#define TILE_B  10240          // 128*40*2 bytes
#define BUF_B   40960          // 4 tiles
#define GEMM_DSMEM (2 * BUF_B) // 81920

template <int KD>
__global__ void __launch_bounds__(256, 1)
moe_gemm_mma(const __nv_bfloat16* __restrict__ Ah, const __nv_bfloat16* __restrict__ Al,
             const __nv_bfloat16* __restrict__ Wh, const __nv_bfloat16* __restrict__ Wl,
             float* __restrict__ Y, const int* __restrict__ cnts,
             const int* __restrict__ gidx, int Ndim) {
    const int e   = blockIdx.z;
    const int cnt = __ldg(&cnts[e]);
    const int m0  = blockIdx.y * 128;
    if (m0 >= cnt) return;
    const int n0  = blockIdx.x * 128;

    extern __shared__ char dsm_raw[];
    const uint32_t dsm = smem_to_u32(dsm_raw);

    __shared__ int toks[128];

    const int tid  = threadIdx.x;
    const int lane = tid & 31;
    const int wid  = tid >> 5;
    const int wm   = wid >> 2;   // 0..1  -> m offset wm*64
    const int wn   = wid & 3;    // 0..3  -> n offset wn*32

    if (tid < 128) {
        int m = m0 + tid;
        toks[tid] = gidx[e * T_TOK + (m < cnt ? m : cnt - 1)];
    }
    __syncthreads();

    const int lr = tid >> 2;     // 0..63 (row base for loads)
    const int lc = tid & 3;      // 0..3  (16B column chunk)

    auto prefetch = [&](int c) {
        const int k0 = c * 32;
        const uint32_t sb = dsm + (uint32_t)(c & 1) * BUF_B;
#pragma unroll
        for (int rep = 0; rep < 2; rep++) {
            int r = lr + rep * 64;
            size_t aoff = (size_t)toks[r] * KD + k0 + lc * 8;
            size_t woff = ((size_t)e * Ndim + n0 + r) * (size_t)KD + k0 + lc * 8;
            uint32_t so = (uint32_t)(r * 40 + lc * 8) * 2;
            CP_ASYNC16(sb + 0 * TILE_B + so, Ah + aoff);
            CP_ASYNC16(sb + 1 * TILE_B + so, Al + aoff);
            CP_ASYNC16(sb + 2 * TILE_B + so, Wh + woff);
            CP_ASYNC16(sb + 3 * TILE_B + so, Wl + woff);
        }
        CP_COMMIT();
    };

    float acc[4][4][4] = {};

    const int NCH = KD / 32;
    prefetch(0);

    for (int c = 0; c < NCH; ++c) {
        if (c + 1 < NCH) { prefetch(c + 1); CP_WAIT(1); }
        else             { CP_WAIT(0); }
        __syncthreads();

        const uint32_t sb = dsm + (uint32_t)(c & 1) * BUF_B;
#pragma unroll
        for (int ks = 0; ks < 32; ks += 16) {
            uint32_t ah[4][4], al[4][4];
#pragma unroll
            for (int mf = 0; mf < 4; mf++) {
                uint32_t row = (uint32_t)(wm * 64 + mf * 16 + (lane & 15));
                uint32_t col = (uint32_t)(ks + ((lane >> 4) << 3));
                uint32_t ad  = sb + (row * 40 + col) * 2;
                ldsm4(ah[mf][0], ah[mf][1], ah[mf][2], ah[mf][3], ad);
                ldsm4(al[mf][0], al[mf][1], al[mf][2], al[mf][3], ad + TILE_B);
            }
            uint32_t bh[2][4], bl[2][4];
#pragma unroll
            for (int np = 0; np < 2; np++) {
                uint32_t nrow = (uint32_t)(wn * 32 + np * 16 + ((lane >> 4) << 3) + (lane & 7));
                uint32_t kcol = (uint32_t)(ks + ((lane >> 3) & 1) * 8);
                uint32_t bd   = sb + 2 * TILE_B + (nrow * 40 + kcol) * 2;
                ldsm4(bh[np][0], bh[np][1], bh[np][2], bh[np][3], bd);
                ldsm4(bl[np][0], bl[np][1], bl[np][2], bl[np][3], bd + TILE_B);
            }
            // pass-outer ordering: 16 independent accs between reuse of any acc
#pragma unroll
            for (int mf = 0; mf < 4; mf++)
#pragma unroll
                for (int nf = 0; nf < 4; nf++)
                    mma16816(acc[mf][nf], ah[mf],
                             bh[nf >> 1][(nf & 1) * 2], bh[nf >> 1][(nf & 1) * 2 + 1]);
#pragma unroll
            for (int mf = 0; mf < 4; mf++)
#pragma unroll
                for (int nf = 0; nf < 4; nf++)
                    mma16816(acc[mf][nf], ah[mf],
                             bl[nf >> 1][(nf & 1) * 2], bl[nf >> 1][(nf & 1) * 2 + 1]);
#pragma unroll
            for (int mf = 0; mf < 4; mf++)
#pragma unroll
                for (int nf = 0; nf < 4; nf++)
                    mma16816(acc[mf][nf], al[mf],
                             bh[nf >> 1][(nf & 1) * 2], bh[nf >> 1][(nf & 1) * 2 + 1]);
        }
        __syncthreads();
    }

    // epilogue: write per-entry outputs (no atomics)
#pragma unroll
    for (int mf = 0; mf < 4; mf++) {
        int mrow = wm * 64 + mf * 16 + (lane >> 2);
        bool live0 = (m0 + mrow) < cnt;
        bool live1 = (m0 + mrow + 8) < cnt;
        float* y0 = Y + ((size_t)e * T_TOK + m0 + mrow) * Ndim + n0 + wn * 32 + (lane & 3) * 2;
#pragma unroll
        for (int nf = 0; nf < 4; nf++) {
            if (live0) {
                float2 v = make_float2(acc[mf][nf][0], acc[mf][nf][1]);
                *reinterpret_cast<float2*>(y0 + nf * 8) = v;
            }
            if (live1) {
                float2 v = make_float2(acc[mf][nf][2], acc[mf][nf][3]);
                *reinterpret_cast<float2*>(y0 + (size_t)8 * Ndim + nf * 8) = v;
            }
        }
    }
}

// ===================== combine kernels =====================
__global__ void combine_bf16_kernel(const float* __restrict__ Y, int s,
                                    const float* __restrict__ bias, int Ndim,
                                    __nv_bfloat16* __restrict__ oh,
                                    __nv_bfloat16* __restrict__ ol) {
    int gid = blockIdx.x * blockDim.x + threadIdx.x;
    int per = Ndim >> 2;
    int t = gid / per;
    if (t >= T_TOK) return;
    int c = (gid - t * per) << 2;
    int2 en = g_ent[s][t];
    float2 w = g_wtk[s][t];
    int e0 = en.x >> 14;
    float4 y0 = *(const float4*)(Y + (size_t)en.x * Ndim + c);
    float4 b0 = *(const float4*)(bias + (size_t)e0 * Ndim + c);
    float4 v;
    v.x = w.x * (y0.x + b0.x); v.y = w.x * (y0.y + b0.y);
    v.z = w.x * (y0.z + b0.z); v.w = w.x * (y0.w + b0.w);
    if (en.y >= 0) {
        int e1 = en.y >> 14;
        float4 y1 = *(const float4*)(Y + (size_t)en.y * Ndim + c);
        float4 b1 = *(const float4*)(bias + (size_t)e1 * Ndim + c);
        v.x += w.y * (y1.x + b1.x); v.y += w.y * (y1.y + b1.y);
        v.z += w.y * (y1.z + b1.z); v.w += w.y * (y1.w + b1.w);
    }
    __nv_bfloat162 h0, l0, h1, l1;
    split2(v.x, v.y, h0, l0);
    split2(v.z, v.w, h1, l1);
    size_t o = (size_t)t * Ndim + c;
    *(__nv_bfloat162*)(oh + o)     = h0;
    *(__nv_bfloat162*)(oh + o + 2) = h1;
    *(__nv_bfloat162*)(ol + o)     = l0;
    *(__nv_bfloat162*)(ol + o + 2) = l1;
}

__global__ void combine_final_kernel(const float* __restrict__ Y, int s,
                                     const float* __restrict__ bias, int Ndim,
                                     float* __restrict__ out) {
    int gid = blockIdx.x * blockDim.x + threadIdx.x;
    int per = Ndim >> 2;
    int t = gid / per;
    if (t >= T_TOK) return;
    int c = (gid - t * per) << 2;
    int2 en = g_ent[s][t];
    float2 w = g_wtk[s][t];
    int e0 = en.x >> 14;
    float4 y0 = *(const float4*)(Y + (size_t)en.x * Ndim + c);
    float4 b0 = *(const float4*)(bias + (size_t)e0 * Ndim + c);
    float4 v;
    v.x = w.x * fmaxf(y0.x + b0.x, 0.f); v.y = w.x * fmaxf(y0.y + b0.y, 0.f);
    v.z = w.x * fmaxf(y0.z + b0.z, 0.f); v.w = w.x * fmaxf(y0.w + b0.w, 0.f);
    if (en.y >= 0) {
        int e1 = en.y >> 14;
        float4 y1 = *(const float4*)(Y + (size_t)en.y * Ndim + c);
        float4 b1 = *(const float4*)(bias + (size_t)e1 * Ndim + c);
        v.x += w.y * fmaxf(y1.x + b1.x, 0.f); v.y += w.y * fmaxf(y1.y + b1.y, 0.f);
        v.z += w.y * fmaxf(y1.z + b1.z, 0.f); v.w += w.y * fmaxf(y1.w + b1.w, 0.f);
    }
    v.x = fmaxf(v.x, 0.f); v.y = fmaxf(v.y, 0.f);
    v.z = fmaxf(v.z, 0.f); v.w = fmaxf(v.w, 0.f);
    *(float4*)(out + (size_t)t * Ndim + c) = v;
}

// ===================== launch =====================
extern "C" void kernel_launch(void* const* d_in, const int* in_sizes, int n_in,
                              void* d_out, int out_size) {
    const float* x   = (const float*)d_in[0];
    const void*  m1  = d_in[1];
    const void*  m2  = d_in[2];
    const void*  m3  = d_in[3];
    const float* rw1 = (const float*)d_in[4];
    const float* rw2 = (const float*)d_in[5];
    const float* rw3 = (const float*)d_in[6];
    const float* W1  = (const float*)d_in[7];
    const float* b1  = (const float*)d_in[8];
    const float* W2  = (const float*)d_in[9];
    const float* b2  = (const float*)d_in[10];
    const float* W3  = (const float*)d_in[11];
    const float* b3  = (const float*)d_in[12];
    float* out = (float*)d_out;

    void* p;
    cudaGetSymbolAddress(&p, g_xh);  __nv_bfloat16* xh  = (__nv_bfloat16*)p;
    cudaGetSymbolAddress(&p, g_xl);  __nv_bfloat16* xl  = (__nv_bfloat16*)p;
    cudaGetSymbolAddress(&p, g_h1h); __nv_bfloat16* h1h = (__nv_bfloat16*)p;
    cudaGetSymbolAddress(&p, g_h1l); __nv_bfloat16* h1l = (__nv_bfloat16*)p;
    cudaGetSymbolAddress(&p, g_h2h); __nv_bfloat16* h2h = (__nv_bfloat16*)p;
    cudaGetSymbolAddress(&p, g_h2l); __nv_bfloat16* h2l = (__nv_bfloat16*)p;
    cudaGetSymbolAddress(&p, g_w1h); __nv_bfloat16* w1h = (__nv_bfloat16*)p;
    cudaGetSymbolAddress(&p, g_w1l); __nv_bfloat16* w1l = (__nv_bfloat16*)p;
    cudaGetSymbolAddress(&p, g_w2h); __nv_bfloat16* w2h = (__nv_bfloat16*)p;
    cudaGetSymbolAddress(&p, g_w2l); __nv_bfloat16* w2l = (__nv_bfloat16*)p;
    cudaGetSymbolAddress(&p, g_w3h); __nv_bfloat16* w3h = (__nv_bfloat16*)p;
    cudaGetSymbolAddress(&p, g_w3l); __nv_bfloat16* w3l = (__nv_bfloat16*)p;
    cudaGetSymbolAddress(&p, g_Y);   float* Y = (float*)p;
    cudaGetSymbolAddress(&p, g_cnt);  int* cnt  = (int*)p;
    cudaGetSymbolAddress(&p, g_idxs); int* idxs = (int*)p;

    cudaFuncSetAttribute(moe_gemm_mma<512>, cudaFuncAttributeMaxDynamicSharedMemorySize, GEMM_DSMEM);
    cudaFuncSetAttribute(moe_gemm_mma<256>, cudaFuncAttributeMaxDynamicSharedMemorySize, GEMM_DSMEM);

    zero_cnt_kernel<<<1, 32>>>();
    detect_count_kernel<<<128, 256>>>((const unsigned char*)m1);
    detect_decide_kernel<<<1, 1>>>((const unsigned char*)m1);
    route3_kernel<<<T_TOK / 256, 256>>>(m1, m2, m3, rw1, rw2, rw3);

    cvt_pair_kernel<<<(T_TOK * 512 / 4) / 256, 256>>>(x, xh, xl, T_TOK * 512 / 4);
    cvt_pair_kernel<<<(E_EXP * 256 * 512 / 4) / 256, 256>>>(W1, w1h, w1l, E_EXP * 256 * 512 / 4);
    cvt_pair_kernel<<<(E_EXP * 256 * 256 / 4) / 256, 256>>>(W2, w2h, w2l, E_EXP * 256 * 256 / 4);
    cvt_pair_kernel<<<(E_EXP * 512 * 256 / 4) / 256, 256>>>(W3, w3h, w3l, E_EXP * 512 * 256 / 4);

    // stage 1: x[.,512] -> Y -> h1 (bf16 pair)
    {
        dim3 grid(256 / 128, T_TOK / 128, E_EXP);
        moe_gemm_mma<512><<<grid, 256, GEMM_DSMEM>>>(xh, xl, w1h, w1l, Y,
                                                     cnt + 0 * E_EXP, idxs + 0 * E_EXP * T_TOK, 256);
        combine_bf16_kernel<<<(T_TOK * 256 / 4) / 256, 256>>>(Y, 0, b1, 256, h1h, h1l);
    }
    // stage 2: h1[.,256] -> Y -> h2 (bf16 pair)
    {
        dim3 grid(256 / 128, T_TOK / 128, E_EXP);
        moe_gemm_mma<256><<<grid, 256, GEMM_DSMEM>>>(h1h, h1l, w2h, w2l, Y,
                                                     cnt + 1 * E_EXP, idxs + 1 * E_EXP * T_TOK, 256);
        combine_bf16_kernel<<<(T_TOK * 256 / 4) / 256, 256>>>(Y, 1, b2, 256, h2h, h2l);
    }
    // stage 3: h2[.,256] -> Y -> out (relu(expert), combine, relu)
    {
        dim3 grid(512 / 128, T_TOK / 128, E_EXP);
        moe_gemm_mma<256><<<grid, 256, GEMM_DSMEM>>>(h2h, h2l, w3h, w3l, Y,
                                                     cnt + 2 * E_EXP, idxs + 2 * E_EXP * T_TOK, 512);
        combine_final_kernel<<<(T_TOK * 512 / 4) / 256, 256>>>(Y, 2, b3, 512, out);
    }
}